// round 10
// baseline (speedup 1.0000x reference)
#include <cuda_runtime.h>
#include <cuda_fp16.h>
#include <math.h>

#define NN 50000
#define EE 1600000
#define DD 128
#define HC 64     // H*C = 2*32
#define NB 196    // ceil(NN/256) scan blocks

// ---- scratch (device globals; no allocation allowed) ----
__device__ __half  g_hh[NN * HC];       // fp16 h = elu(x) @ W      6.4 MB
__device__ float   g_asrc[NN * 2];
__device__ float   g_adst[NN * 2];
__device__ float2  g_nwcnt[NN];         // {sum w, count} per source node
__device__ int     g_deg[NN];           // in-degree (excl self loop)
__device__ int     g_off[NN];           // block-local exclusive scan
__device__ int     g_cursor[NN];        // scatter cursors (end-of-segment after scatter)
__device__ int     g_bsum[256];
__device__ uint2   g_sorted[EE];        // {src, as01:half2}  12.8 MB

__device__ __forceinline__ float lrelu(float a) { return a > 0.0f ? a : 0.2f * a; }
__device__ __forceinline__ float elu_f(float v) { return v > 0.0f ? v : (__expf(v) - 1.0f); }

__device__ __forceinline__ void fma4(float4& acc, const float4 wv, const float xs) {
    acc.x += xs * wv.x; acc.y += xs * wv.y; acc.z += xs * wv.z; acc.w += xs * wv.w;
}
__device__ __forceinline__ float dot4(const float4 a, const float4 b) {
    return a.x*b.x + a.y*b.y + a.z*b.z + a.w*b.w;
}

// ---------------- 1) h = elu(x) @ W, register-blocked 4x8, fused attention dots ----------------
__global__ void k_gemm(const float* __restrict__ x, const float* __restrict__ W,
                       const float* __restrict__ att_src, const float* __restrict__ att_dst) {
    __shared__ float sW[DD * HC];                 // 32 KB
    __shared__ float sAs[HC], sAd[HC];
    int tid = threadIdx.x;                        // 256 threads
    const float4* Wv = (const float4*)W;
    float4* sWv = (float4*)sW;
#pragma unroll
    for (int i = 0; i < 8; i++) sWv[tid + i * 256] = Wv[tid + i * 256];
    if (tid < HC) { sAs[tid] = att_src[tid]; sAd[tid] = att_dst[tid]; }
    __syncthreads();

    int cg = tid & 7;                             // 8 cols starting at cg*8
    int rg = tid >> 3;                            // 0..31, 4 rows each
    int rb = blockIdx.x * 128 + rg * 4;

    float4 a[4][2];
#pragma unroll
    for (int i = 0; i < 4; i++) { a[i][0] = make_float4(0,0,0,0); a[i][1] = make_float4(0,0,0,0); }

    const float4* xp[4];
#pragma unroll
    for (int i = 0; i < 4; i++) {
        int r = rb + i; if (r >= NN) r = NN - 1;
        xp[i] = (const float4*)(x + (size_t)r * DD);
    }

#pragma unroll 2
    for (int k4 = 0; k4 < 32; k4++) {
        float4 xv[4];
#pragma unroll
        for (int i = 0; i < 4; i++) {
            float4 v = __ldg(&xp[i][k4]);
            v.x = elu_f(v.x); v.y = elu_f(v.y); v.z = elu_f(v.z); v.w = elu_f(v.w);
            xv[i] = v;
        }
#pragma unroll
        for (int j = 0; j < 4; j++) {
            const float4* wr = (const float4*)&sW[(k4 * 4 + j) * HC + cg * 8];
            float4 w0 = wr[0], w1 = wr[1];
#pragma unroll
            for (int i = 0; i < 4; i++) {
                float xs = (j == 0) ? xv[i].x : (j == 1) ? xv[i].y : (j == 2) ? xv[i].z : xv[i].w;
                fma4(a[i][0], w0, xs);
                fma4(a[i][1], w1, xs);
            }
        }
    }

    float4 s0 = ((const float4*)sAs)[cg * 2], s1 = ((const float4*)sAs)[cg * 2 + 1];
    float4 d0 = ((const float4*)sAd)[cg * 2], d1 = ((const float4*)sAd)[cg * 2 + 1];
    float asp[4], adp[4];
#pragma unroll
    for (int i = 0; i < 4; i++) {
        asp[i] = dot4(a[i][0], s0) + dot4(a[i][1], s1);
        adp[i] = dot4(a[i][0], d0) + dot4(a[i][1], d1);
    }
#pragma unroll
    for (int off = 1; off <= 2; off <<= 1) {
#pragma unroll
        for (int i = 0; i < 4; i++) {
            asp[i] += __shfl_xor_sync(0xffffffff, asp[i], off);
            adp[i] += __shfl_xor_sync(0xffffffff, adp[i], off);
        }
    }
    if ((cg & 3) == 0) {
        int head = cg >> 2;
#pragma unroll
        for (int i = 0; i < 4; i++) {
            int r = rb + i;
            if (r < NN) {
                g_asrc[2*r + head] = asp[i];
                g_adst[2*r + head] = adp[i];
            }
        }
    }

#pragma unroll
    for (int i = 0; i < 4; i++) {
        int r = rb + i;
        if (r < NN) {
            __half2* hp = (__half2*)(g_hh + (size_t)r * HC + cg * 8);
            hp[0] = __floats2half2_rn(a[i][0].x, a[i][0].y);
            hp[1] = __floats2half2_rn(a[i][0].z, a[i][0].w);
            hp[2] = __floats2half2_rn(a[i][1].x, a[i][1].y);
            hp[3] = __floats2half2_rn(a[i][1].z, a[i][1].w);
        }
    }
}

// ---------------- 0) zero the accumulators used by hist (side-stream branch head) ----------------
__global__ void k_zero() {
    int n = blockIdx.x * blockDim.x + threadIdx.x;
    if (n >= NN) return;
    g_nwcnt[n] = make_float2(0.0f, 0.0f);
    g_deg[n] = 0;
}

// ---------------- 2) histogram (2 edges/thread): deg[dst]++, nwcnt[src] += {w,1} ----------------
__global__ void k_hist(const int* __restrict__ ei, const float* __restrict__ wgt) {
    int e2 = blockIdx.x * blockDim.x + threadIdx.x;
    if (e2 >= EE / 2) return;
    int2   ss = __ldg((const int2*)ei + e2);
    int2   dd = __ldg((const int2*)(ei + EE) + e2);
    float2 ww = __ldg((const float2*)wgt + e2);
    atomicAdd(&g_deg[dd.x], 1);
    atomicAdd(&g_deg[dd.y], 1);
    asm volatile("red.global.add.v2.f32 [%0], {%1,%2};"
                 :: "l"((float*)(g_nwcnt + ss.x)), "f"(ww.x), "f"(1.0f) : "memory");
    asm volatile("red.global.add.v2.f32 [%0], {%1,%2};"
                 :: "l"((float*)(g_nwcnt + ss.y)), "f"(ww.y), "f"(1.0f) : "memory");
}

// ---------------- 3) two-kernel scan ----------------
__global__ void k_scan1() {
    int tid = threadIdx.x, lane = tid & 31, w = tid >> 5;
    int i = blockIdx.x * 256 + tid;
    int v = (i < NN) ? g_deg[i] : 0;
    int s = v;
#pragma unroll
    for (int off = 1; off < 32; off <<= 1) {
        int t = __shfl_up_sync(0xffffffff, s, off);
        if (lane >= off) s += t;
    }
    __shared__ int ws[8];
    if (lane == 31) ws[w] = s;
    __syncthreads();
    int woff = 0;
#pragma unroll
    for (int k = 0; k < 8; k++) woff += (k < w) ? ws[k] : 0;
    if (i < NN) g_off[i] = s - v + woff;
    if (tid == 255) g_bsum[blockIdx.x] = s + woff;
}
// block b adds sum(bsum[0..b-1]) — a reduction, not a scan
__global__ void k_scan3() {
    __shared__ int ws[8];
    int tid = threadIdx.x, lane = tid & 31, w = tid >> 5;
    int b = blockIdx.x;
    int v = (tid < b) ? g_bsum[tid] : 0;   // b <= NB-1 < 256
#pragma unroll
    for (int off = 16; off >= 1; off >>= 1) v += __shfl_xor_sync(0xffffffff, v, off);
    if (lane == 0) ws[w] = v;
    __syncthreads();
    int prev = 0;
#pragma unroll
    for (int k = 0; k < 8; k++) prev += ws[k];
    int i = b * 256 + tid;
    if (i < NN) g_cursor[i] = g_off[i] + prev;
}

// ---------------- 4) scatter: 8B records {src, as01:half2} sorted by dst ----------------
__global__ void k_scatter(const int* __restrict__ ei) {
    int e = blockIdx.x * blockDim.x + threadIdx.x;
    if (e >= EE) return;
    int s = __ldg(&ei[e]);
    int d = __ldg(&ei[EE + e]);
    float2 as = __ldg((const float2*)(g_asrc + 2 * s));
    __half2 ah = __floats2half2_rn(as.x, as.y);
    uint2 rec;
    rec.x = (unsigned)s;
    rec.y = *(unsigned*)&ah;
    int pos = atomicAdd(&g_cursor[d], 1);
    g_sorted[pos] = rec;
}

// ---------------- 5) gather: one warp per dst, 8-record batches, pipelined ----------------
__global__ void k_gather(float* __restrict__ out, const float* __restrict__ bias,
                         const float* __restrict__ esc) {
    int warp_in_block = threadIdx.x >> 5;
    int lane = threadIdx.x & 31;
    int n = blockIdx.x * 8 + warp_in_block;
    if (n >= NN) return;

    int head = lane >> 4;                 // lanes 0-15: head0, 16-31: head1
    int cnt   = g_deg[n];
    int start = g_cursor[n] - cnt;        // cursor is end-of-segment after scatter

    float2 adv = __ldg((const float2*)(g_adst + 2 * n));
    int t16 = lane & 15;
    int qq  = t16 >> 1;                   // record slot (0..7) this lane exps
    int hs  = t16 & 1;                    // head slot
    float ad_sel = hs ? adv.y : adv.x;
    float ad_me  = head ? adv.y : adv.x;

    float2 acc = make_float2(0.0f, 0.0f);
    float den = 0.0f;
    const __half2* hh = (const __half2*)g_hh;
    const uint2* rec = g_sorted + start;

    int nq = cnt >> 3, rem = cnt & 7;
    uint2 r[8];
    if (nq) {
#pragma unroll
        for (int i = 0; i < 8; i++) r[i] = __ldg(rec + i);
    }
    for (int q = 0; q < nq; q++) {
        __half2 v[8];
#pragma unroll
        for (int i = 0; i < 8; i++) v[i] = __ldg(hh + (size_t)r[i].x * 32 + lane);

        // one warp-wide exp covers all 16 (record, head) slots in lanes 0-15
        unsigned ab = r[0].y;
#pragma unroll
        for (int i = 1; i < 8; i++) ab = (qq == i) ? r[i].y : ab;
        float2 af = __half22float2(*(__half2*)&ab);
        float ev = __expf(lrelu((hs ? af.y : af.x) + ad_sel));
        float e[8];
#pragma unroll
        for (int i = 0; i < 8; i++) e[i] = __shfl_sync(0xffffffff, ev, 2 * i + head);

        bool more = (q + 1 < nq);
        uint2 nr[8];
        if (more) {
            const uint2* p = rec + 8 * (q + 1);
#pragma unroll
            for (int i = 0; i < 8; i++) nr[i] = __ldg(p + i);
        }
#pragma unroll
        for (int i = 0; i < 8; i++) {
            float2 f = __half22float2(v[i]);
            acc.x += e[i] * f.x;
            acc.y += e[i] * f.y;
            den   += e[i];
        }
        if (more) {
#pragma unroll
            for (int i = 0; i < 8; i++) r[i] = nr[i];
        }
    }
    const uint2* tp = rec + nq * 8;
    for (int k = 0; k < rem; k++) {
        uint2 rr = __ldg(tp + k);
        __half2 v = __ldg(hh + (size_t)rr.x * 32 + lane);
        float2 af = __half22float2(*(__half2*)&rr.y);
        float e0 = __expf(lrelu((head ? af.y : af.x) + ad_me));
        float2 f = __half22float2(v);
        acc.x += e0 * f.x; acc.y += e0 * f.y;
        den += e0;
    }

    // self loop (fp32 logits)
    float a_self = lrelu(g_asrc[2*n + head] + ad_me);
    float e_self = __expf(a_self);
    float2 hsv = __half22float2(__ldg(hh + (size_t)n * 32 + lane));
    acc.x += e_self * hsv.x; acc.y += e_self * hsv.y;
    den += e_self;

    float rd = __frcp_rn(den);

    float2 nwc = g_nwcnt[n];
    float nw = nwc.x / fmaxf(nwc.y, 1.0f);
    nw = fminf(fmaxf(nw, 0.2f), 5.0f);
    float sf  = 0.1f / (1.0f + __expf(-esc[0]));
    float add = sf * (nw - 1.0f);

    float2 b2 = *(const float2*)(bias + 2 * lane);
    float2 o;
    o.x = acc.x * rd + b2.x + add;
    o.y = acc.y * rd + b2.y + add;
    *(float2*)(out + (size_t)n * HC + 2 * lane) = o;
}

extern "C" void kernel_launch(void* const* d_in, const int* in_sizes, int n_in,
                              void* d_out, int out_size) {
    const float* x       = (const float*)d_in[0];
    const int*   ei      = (const int*)  d_in[1];
    const float* wgt     = (const float*)d_in[2];
    const float* W       = (const float*)d_in[3];
    const float* att_src = (const float*)d_in[4];
    const float* att_dst = (const float*)d_in[5];
    const float* bias    = (const float*)d_in[6];
    const float* esc     = (const float*)d_in[7];
    float* out = (float*)d_out;
    (void)in_sizes; (void)n_in; (void)out_size;

    // Fork-join: side stream runs zero->hist->scan while main stream runs gemm.
    // Streams/events are created per call and intentionally not destroyed
    // (host-side objects only; kernel_launch runs twice, no device memory involved,
    // destroying a forked stream mid-capture would invalidate the capture).
    cudaStream_t sB;
    cudaEvent_t evF, evJ;
    cudaStreamCreateWithFlags(&sB, cudaStreamNonBlocking);
    cudaEventCreateWithFlags(&evF, cudaEventDisableTiming);
    cudaEventCreateWithFlags(&evJ, cudaEventDisableTiming);

    cudaEventRecord(evF, 0);              // fork from the (captured) main stream
    cudaStreamWaitEvent(sB, evF, 0);

    k_zero  <<<(NN + 255) / 256,     256, 0, sB>>>();
    k_hist  <<<(EE / 2 + 255) / 256, 256, 0, sB>>>(ei, wgt);
    k_scan1 <<<NB,                   256, 0, sB>>>();
    k_scan3 <<<NB,                   256, 0, sB>>>();
    cudaEventRecord(evJ, sB);

    k_gemm  <<<(NN + 127) / 128, 256>>>(x, W, att_src, att_dst);  // main stream, parallel

    cudaStreamWaitEvent(0, evJ, 0);       // join
    k_scatter <<<(EE + 255) / 256, 256>>>(ei);
    k_gather  <<<(NN + 7) / 8,     256>>>(out, bias, esc);
}

// round 11
// speedup vs baseline: 1.5062x; 1.5062x over previous
#include <cuda_runtime.h>
#include <cuda_fp16.h>
#include <math.h>

#define NN 50000
#define EE 1600000
#define DD 128
#define HC 64     // H*C = 2*32
#define NB 196    // ceil(NN/256) scan blocks

// ---- scratch (device globals; no allocation allowed) ----
__device__ __half  g_hh[NN * HC];       // fp16 h = elu(x) @ W      6.4 MB
__device__ float   g_asrc[NN * 2];
__device__ float   g_adst[NN * 2];
__device__ float2  g_nwcnt[NN];         // {sum w, count} per source node
__device__ int     g_deg[NN];           // in-degree (excl self loop)
__device__ int     g_off[NN];           // block-local exclusive scan
__device__ int     g_cursor[NN];        // scatter cursors (end-of-segment after scatter)
__device__ int     g_bsum[256];
__device__ uint2   g_sorted[EE];        // {src, as01:half2}  12.8 MB

__device__ __forceinline__ float lrelu(float a) { return a > 0.0f ? a : 0.2f * a; }
__device__ __forceinline__ float elu_f(float v) { return v > 0.0f ? v : (__expf(v) - 1.0f); }

__device__ __forceinline__ void fma4(float4& acc, const float4 wv, const float xs) {
    acc.x += xs * wv.x; acc.y += xs * wv.y; acc.z += xs * wv.z; acc.w += xs * wv.w;
}
__device__ __forceinline__ float dot4(const float4 a, const float4 b) {
    return a.x*b.x + a.y*b.y + a.z*b.z + a.w*b.w;
}

// ---------------- 1) h = elu(x) @ W, register-blocked 4x8, fused attention dots ----------------
__global__ void k_gemm(const float* __restrict__ x, const float* __restrict__ W,
                       const float* __restrict__ att_src, const float* __restrict__ att_dst) {
    __shared__ float sW[DD * HC];                 // 32 KB
    __shared__ float sAs[HC], sAd[HC];
    int tid = threadIdx.x;                        // 256 threads
    const float4* Wv = (const float4*)W;
    float4* sWv = (float4*)sW;
#pragma unroll
    for (int i = 0; i < 8; i++) sWv[tid + i * 256] = Wv[tid + i * 256];
    if (tid < HC) { sAs[tid] = att_src[tid]; sAd[tid] = att_dst[tid]; }
    __syncthreads();

    int cg = tid & 7;                             // 8 cols starting at cg*8
    int rg = tid >> 3;                            // 0..31, 4 rows each
    int rb = blockIdx.x * 128 + rg * 4;

    float4 a[4][2];
#pragma unroll
    for (int i = 0; i < 4; i++) { a[i][0] = make_float4(0,0,0,0); a[i][1] = make_float4(0,0,0,0); }

    const float4* xp[4];
#pragma unroll
    for (int i = 0; i < 4; i++) {
        int r = rb + i; if (r >= NN) r = NN - 1;
        xp[i] = (const float4*)(x + (size_t)r * DD);
    }

#pragma unroll 2
    for (int k4 = 0; k4 < 32; k4++) {
        float4 xv[4];
#pragma unroll
        for (int i = 0; i < 4; i++) {
            float4 v = __ldg(&xp[i][k4]);
            v.x = elu_f(v.x); v.y = elu_f(v.y); v.z = elu_f(v.z); v.w = elu_f(v.w);
            xv[i] = v;
        }
#pragma unroll
        for (int j = 0; j < 4; j++) {
            const float4* wr = (const float4*)&sW[(k4 * 4 + j) * HC + cg * 8];
            float4 w0 = wr[0], w1 = wr[1];
#pragma unroll
            for (int i = 0; i < 4; i++) {
                float xs = (j == 0) ? xv[i].x : (j == 1) ? xv[i].y : (j == 2) ? xv[i].z : xv[i].w;
                fma4(a[i][0], w0, xs);
                fma4(a[i][1], w1, xs);
            }
        }
    }

    float4 s0 = ((const float4*)sAs)[cg * 2], s1 = ((const float4*)sAs)[cg * 2 + 1];
    float4 d0 = ((const float4*)sAd)[cg * 2], d1 = ((const float4*)sAd)[cg * 2 + 1];
    float asp[4], adp[4];
#pragma unroll
    for (int i = 0; i < 4; i++) {
        asp[i] = dot4(a[i][0], s0) + dot4(a[i][1], s1);
        adp[i] = dot4(a[i][0], d0) + dot4(a[i][1], d1);
    }
#pragma unroll
    for (int off = 1; off <= 2; off <<= 1) {
#pragma unroll
        for (int i = 0; i < 4; i++) {
            asp[i] += __shfl_xor_sync(0xffffffff, asp[i], off);
            adp[i] += __shfl_xor_sync(0xffffffff, adp[i], off);
        }
    }
    if ((cg & 3) == 0) {
        int head = cg >> 2;
#pragma unroll
        for (int i = 0; i < 4; i++) {
            int r = rb + i;
            if (r < NN) {
                g_asrc[2*r + head] = asp[i];
                g_adst[2*r + head] = adp[i];
                if (head == 0) { g_nwcnt[r] = make_float2(0.0f, 0.0f); g_deg[r] = 0; }
            }
        }
    }

#pragma unroll
    for (int i = 0; i < 4; i++) {
        int r = rb + i;
        if (r < NN) {
            __half2* hp = (__half2*)(g_hh + (size_t)r * HC + cg * 8);
            hp[0] = __floats2half2_rn(a[i][0].x, a[i][0].y);
            hp[1] = __floats2half2_rn(a[i][0].z, a[i][0].w);
            hp[2] = __floats2half2_rn(a[i][1].x, a[i][1].y);
            hp[3] = __floats2half2_rn(a[i][1].z, a[i][1].w);
        }
    }
}

// ---------------- 2) histogram (2 edges/thread): deg[dst]++, nwcnt[src] += {w,1} ----------------
__global__ void k_hist(const int* __restrict__ ei, const float* __restrict__ wgt) {
    int e2 = blockIdx.x * blockDim.x + threadIdx.x;
    if (e2 >= EE / 2) return;
    int2   ss = __ldg((const int2*)ei + e2);
    int2   dd = __ldg((const int2*)(ei + EE) + e2);
    float2 ww = __ldg((const float2*)wgt + e2);
    atomicAdd(&g_deg[dd.x], 1);
    atomicAdd(&g_deg[dd.y], 1);
    asm volatile("red.global.add.v2.f32 [%0], {%1,%2};"
                 :: "l"((float*)(g_nwcnt + ss.x)), "f"(ww.x), "f"(1.0f) : "memory");
    asm volatile("red.global.add.v2.f32 [%0], {%1,%2};"
                 :: "l"((float*)(g_nwcnt + ss.y)), "f"(ww.y), "f"(1.0f) : "memory");
}

// ---------------- 3) two-kernel scan ----------------
__global__ void k_scan1() {
    int tid = threadIdx.x, lane = tid & 31, w = tid >> 5;
    int i = blockIdx.x * 256 + tid;
    int v = (i < NN) ? g_deg[i] : 0;
    int s = v;
#pragma unroll
    for (int off = 1; off < 32; off <<= 1) {
        int t = __shfl_up_sync(0xffffffff, s, off);
        if (lane >= off) s += t;
    }
    __shared__ int ws[8];
    if (lane == 31) ws[w] = s;
    __syncthreads();
    int woff = 0;
#pragma unroll
    for (int k = 0; k < 8; k++) woff += (k < w) ? ws[k] : 0;
    if (i < NN) g_off[i] = s - v + woff;
    if (tid == 255) g_bsum[blockIdx.x] = s + woff;
}
// block b adds sum(bsum[0..b-1]) — a reduction, not a scan
__global__ void k_scan3() {
    __shared__ int ws[8];
    int tid = threadIdx.x, lane = tid & 31, w = tid >> 5;
    int b = blockIdx.x;
    int v = (tid < b) ? g_bsum[tid] : 0;   // b <= NB-1 < 256
#pragma unroll
    for (int off = 16; off >= 1; off >>= 1) v += __shfl_xor_sync(0xffffffff, v, off);
    if (lane == 0) ws[w] = v;
    __syncthreads();
    int prev = 0;
#pragma unroll
    for (int k = 0; k < 8; k++) prev += ws[k];
    int i = b * 256 + tid;
    if (i < NN) g_cursor[i] = g_off[i] + prev;
}

// ---------------- 4) scatter: 8B records {src, as01:half2} sorted by dst ----------------
__global__ void k_scatter(const int* __restrict__ ei) {
    int e = blockIdx.x * blockDim.x + threadIdx.x;
    if (e >= EE) return;
    int s = __ldg(&ei[e]);
    int d = __ldg(&ei[EE + e]);
    float2 as = __ldg((const float2*)(g_asrc + 2 * s));
    __half2 ah = __floats2half2_rn(as.x, as.y);
    uint2 rec;
    rec.x = (unsigned)s;
    rec.y = *(unsigned*)&ah;
    int pos = atomicAdd(&g_cursor[d], 1);
    g_sorted[pos] = rec;
}

// ---------------- 5) gather: one warp per dst, lane-sliced record loads, pipelined ----------------
__global__ void k_gather(float* __restrict__ out, const float* __restrict__ bias,
                         const float* __restrict__ esc) {
    int warp_in_block = threadIdx.x >> 5;
    int lane = threadIdx.x & 31;
    int n = blockIdx.x * 8 + warp_in_block;
    if (n >= NN) return;

    int head = lane >> 4;                 // lanes 0-15: head0, 16-31: head1
    int cnt   = g_deg[n];
    int start = g_cursor[n] - cnt;        // cursor is end-of-segment after scatter

    float2 adv = __ldg((const float2*)(g_adst + 2 * n));
    int t16 = lane & 15;
    int qq  = t16 >> 1;                   // record slot (0..7) this lane exps
    int hs  = t16 & 1;                    // head slot
    float ad_sel = hs ? adv.y : adv.x;
    float ad_me  = head ? adv.y : adv.x;

    float2 acc = make_float2(0.0f, 0.0f);
    float den = 0.0f;
    const __half2* hh = (const __half2*)g_hh;
    const uint2* rec = g_sorted + start;

    int nq = cnt >> 3, rem = cnt & 7;
    int l8 = lane & 7;
    uint2 myr;                            // lane l8 holds record l8 of current batch
    if (nq) myr = __ldg(rec + l8);
    for (int q = 0; q < nq; q++) {
        // broadcast the 8 src indices from lanes 0-7
        unsigned s[8];
#pragma unroll
        for (int i = 0; i < 8; i++) s[i] = __shfl_sync(0xffffffff, myr.x, i);
        // coalesced h loads
        __half2 v[8];
#pragma unroll
        for (int i = 0; i < 8; i++) v[i] = __ldg(hh + (size_t)s[i] * 32 + lane);

        // exp: lane t16 handles (record qq, head hs); one warp-wide MUFU covers 16 slots
        unsigned ab = __shfl_sync(0xffffffff, myr.y, qq);
        float2 af = __half22float2(*(__half2*)&ab);
        float ev = __expf(lrelu((hs ? af.y : af.x) + ad_sel));
        float e[8];
#pragma unroll
        for (int i = 0; i < 8; i++) e[i] = __shfl_sync(0xffffffff, ev, 2 * i + head);

        // prefetch next batch's records (lane-sliced)
        bool more = (q + 1 < nq);
        uint2 nmyr;
        if (more) nmyr = __ldg(rec + 8 * (q + 1) + l8);

#pragma unroll
        for (int i = 0; i < 8; i++) {
            float2 f = __half22float2(v[i]);
            acc.x += e[i] * f.x;
            acc.y += e[i] * f.y;
            den   += e[i];
        }
        if (more) myr = nmyr;
    }
    const uint2* tp = rec + nq * 8;
    for (int k = 0; k < rem; k++) {
        uint2 rr = __ldg(tp + k);
        __half2 v = __ldg(hh + (size_t)rr.x * 32 + lane);
        float2 af = __half22float2(*(__half2*)&rr.y);
        float e0 = __expf(lrelu((head ? af.y : af.x) + ad_me));
        float2 f = __half22float2(v);
        acc.x += e0 * f.x; acc.y += e0 * f.y;
        den += e0;
    }

    // self loop (fp32 logits)
    float a_self = lrelu(g_asrc[2*n + head] + ad_me);
    float e_self = __expf(a_self);
    float2 hsv = __half22float2(__ldg(hh + (size_t)n * 32 + lane));
    acc.x += e_self * hsv.x; acc.y += e_self * hsv.y;
    den += e_self;

    float rd = __frcp_rn(den);

    float2 nwc = g_nwcnt[n];
    float nw = nwc.x / fmaxf(nwc.y, 1.0f);
    nw = fminf(fmaxf(nw, 0.2f), 5.0f);
    float sf  = 0.1f / (1.0f + __expf(-esc[0]));
    float add = sf * (nw - 1.0f);

    float2 b2 = *(const float2*)(bias + 2 * lane);
    float2 o;
    o.x = acc.x * rd + b2.x + add;
    o.y = acc.y * rd + b2.y + add;
    *(float2*)(out + (size_t)n * HC + 2 * lane) = o;
}

extern "C" void kernel_launch(void* const* d_in, const int* in_sizes, int n_in,
                              void* d_out, int out_size) {
    const float* x       = (const float*)d_in[0];
    const int*   ei      = (const int*)  d_in[1];
    const float* wgt     = (const float*)d_in[2];
    const float* W       = (const float*)d_in[3];
    const float* att_src = (const float*)d_in[4];
    const float* att_dst = (const float*)d_in[5];
    const float* bias    = (const float*)d_in[6];
    const float* esc     = (const float*)d_in[7];
    float* out = (float*)d_out;
    (void)in_sizes; (void)n_in; (void)out_size;

    k_gemm    <<<(NN + 127) / 128,     256>>>(x, W, att_src, att_dst);
    k_hist    <<<(EE / 2 + 255) / 256, 256>>>(ei, wgt);
    k_scan1   <<<NB,                   256>>>();
    k_scan3   <<<NB,                   256>>>();
    k_scatter <<<(EE + 255) / 256,     256>>>(ei);
    k_gather  <<<(NN + 7) / 8,         256>>>(out, bias, esc);
}

// round 13
// speedup vs baseline: 1.6553x; 1.0990x over previous
#include <cuda_runtime.h>
#include <cuda_fp16.h>
#include <mma.h>
#include <math.h>

using namespace nvcuda;

#define NN 50000
#define EE 1600000
#define DD 128
#define HC 64     // H*C = 2*32
#define NB 196    // ceil(NN/256) scan blocks
#define GB 391    // ceil(NN/128) gemm blocks
#define XSTRIDE 40
// dyn smem: sW 8192 floats (32KB) + sX 128*40 floats (20KB); sOut 8192 floats reuses [0..)
#define SMEM_FLOATS (8192 + 128 * XSTRIDE)

// ---- scratch (device globals; no allocation allowed) ----
__device__ __half  g_hh[NN * HC];       // fp16 h = elu(x) @ W      6.4 MB
__device__ float   g_asrc[NN * 2];
__device__ float   g_adst[NN * 2];
__device__ float2  g_nwcnt[NN];         // {sum w, count} per source node
__device__ int     g_deg[NN];           // in-degree (excl self loop)
__device__ int     g_off[NN];           // block-local exclusive scan
__device__ int     g_cursor[NN];        // scatter cursors (end-of-segment after scatter)
__device__ int     g_bsum[256];
__device__ uint2   g_sorted[EE];        // {src, as01:half2}  12.8 MB

__device__ __forceinline__ float lrelu(float a) { return a > 0.0f ? a : 0.2f * a; }
__device__ __forceinline__ float elu_f(float v) { return v > 0.0f ? v : (__expf(v) - 1.0f); }

// ---------------- 1) h = elu(x) @ W via tf32 wmma; fused dots + fp16 mirror ----------------
__global__ void k_gemm_tc(const float* __restrict__ x, const float* __restrict__ W,
                          const float* __restrict__ att_src, const float* __restrict__ att_dst) {
    extern __shared__ float sm[];
    float* sW   = sm;                    // [128][64]  (tf32-rounded)
    float* sX   = sm + 8192;             // [128][XSTRIDE], 32 K-cols per chunk
    float* sOut = sm;                    // [128][64]  (reuses sW region after MMAs)

    int tid  = threadIdx.x;              // 256 threads = 8 warps
    int wid  = tid >> 5;
    int rb   = blockIdx.x * 128;         // block's first row

    // W -> smem with tf32 rounding (128*64 floats, 2048 float4)
    {
        const float4* Wv = (const float4*)W;
        float4* sWv = (float4*)sW;
#pragma unroll
        for (int i = 0; i < 8; i++) {
            float4 v = Wv[tid + i * 256];
            v.x = wmma::__float_to_tf32(v.x);
            v.y = wmma::__float_to_tf32(v.y);
            v.z = wmma::__float_to_tf32(v.z);
            v.w = wmma::__float_to_tf32(v.w);
            sWv[tid + i * 256] = v;
        }
    }

    wmma::fragment<wmma::accumulator, 16, 16, 8, float> acc[4];
#pragma unroll
    for (int f = 0; f < 4; f++) wmma::fill_fragment(acc[f], 0.0f);

    for (int chunk = 0; chunk < 4; chunk++) {
        __syncthreads();
        // stage x[rb..rb+128][chunk*32..+32] with elu + tf32 round; 4 float4 per thread
#pragma unroll
        for (int i = 0; i < 4; i++) {
            int idx = tid + i * 256;          // 0..1023
            int row = idx >> 3;               // 0..127
            int c4  = idx & 7;                // 0..7
            int gr  = rb + row; if (gr >= NN) gr = NN - 1;
            float4 v = __ldg((const float4*)(x + (size_t)gr * DD + chunk * 32 + c4 * 4));
            v.x = wmma::__float_to_tf32(elu_f(v.x));
            v.y = wmma::__float_to_tf32(elu_f(v.y));
            v.z = wmma::__float_to_tf32(elu_f(v.z));
            v.w = wmma::__float_to_tf32(elu_f(v.w));
            *(float4*)(sX + row * XSTRIDE + c4 * 4) = v;
        }
        __syncthreads();

#pragma unroll
        for (int ks = 0; ks < 4; ks++) {
            wmma::fragment<wmma::matrix_a, 16, 16, 8, wmma::precision::tf32, wmma::row_major> af;
            wmma::load_matrix_sync(af, sX + wid * 16 * XSTRIDE + ks * 8, XSTRIDE);
#pragma unroll
            for (int nf = 0; nf < 4; nf++) {
                wmma::fragment<wmma::matrix_b, 16, 16, 8, wmma::precision::tf32, wmma::row_major> bf;
                wmma::load_matrix_sync(bf, sW + (chunk * 32 + ks * 8) * HC + nf * 16, HC);
                wmma::mma_sync(acc[nf], af, bf, acc[nf]);
            }
        }
    }
    __syncthreads();   // all MMAs done; sW region free -> sOut
#pragma unroll
    for (int nf = 0; nf < 4; nf++)
        wmma::store_matrix_sync(sOut + wid * 16 * HC + nf * 16, acc[nf], HC, wmma::mem_row_major);
    __syncthreads();

    // epilogue: thread t -> row = t>>1, head = t&1 (32 cols)
    {
        int row  = tid >> 1;
        int head = tid & 1;
        int r = rb + row;
        if (r < NN) {
            const float* hrow = sOut + row * HC + head * 32;
            float as = 0.0f, ad = 0.0f;
            __half2 hv[16];
#pragma unroll
            for (int k = 0; k < 32; k += 2) {
                float h0 = hrow[k], h1 = hrow[k + 1];
                as += h0 * __ldg(att_src + head * 32 + k) + h1 * __ldg(att_src + head * 32 + k + 1);
                ad += h0 * __ldg(att_dst + head * 32 + k) + h1 * __ldg(att_dst + head * 32 + k + 1);
                hv[k >> 1] = __floats2half2_rn(h0, h1);
            }
            g_asrc[2 * r + head] = as;
            g_adst[2 * r + head] = ad;
            uint4* hp = (uint4*)(g_hh + (size_t)r * HC + head * 32);
#pragma unroll
            for (int q = 0; q < 4; q++)
                hp[q] = make_uint4(*(unsigned*)&hv[4*q], *(unsigned*)&hv[4*q+1],
                                   *(unsigned*)&hv[4*q+2], *(unsigned*)&hv[4*q+3]);
            if (head == 0) { g_nwcnt[r] = make_float2(0.0f, 0.0f); g_deg[r] = 0; }
        }
    }
}

// ---------------- 2) histogram (2 edges/thread): deg[dst]++, nwcnt[src] += {w,1} ----------------
__global__ void k_hist(const int* __restrict__ ei, const float* __restrict__ wgt) {
    int e2 = blockIdx.x * blockDim.x + threadIdx.x;
    if (e2 >= EE / 2) return;
    int2   ss = __ldg((const int2*)ei + e2);
    int2   dd = __ldg((const int2*)(ei + EE) + e2);
    float2 ww = __ldg((const float2*)wgt + e2);
    atomicAdd(&g_deg[dd.x], 1);
    atomicAdd(&g_deg[dd.y], 1);
    asm volatile("red.global.add.v2.f32 [%0], {%1,%2};"
                 :: "l"((float*)(g_nwcnt + ss.x)), "f"(ww.x), "f"(1.0f) : "memory");
    asm volatile("red.global.add.v2.f32 [%0], {%1,%2};"
                 :: "l"((float*)(g_nwcnt + ss.y)), "f"(ww.y), "f"(1.0f) : "memory");
}

// ---------------- 3) two-kernel scan ----------------
__global__ void k_scan1() {
    int tid = threadIdx.x, lane = tid & 31, w = tid >> 5;
    int i = blockIdx.x * 256 + tid;
    int v = (i < NN) ? g_deg[i] : 0;
    int s = v;
#pragma unroll
    for (int off = 1; off < 32; off <<= 1) {
        int t = __shfl_up_sync(0xffffffff, s, off);
        if (lane >= off) s += t;
    }
    __shared__ int ws[8];
    if (lane == 31) ws[w] = s;
    __syncthreads();
    int woff = 0;
#pragma unroll
    for (int k = 0; k < 8; k++) woff += (k < w) ? ws[k] : 0;
    if (i < NN) g_off[i] = s - v + woff;
    if (tid == 255) g_bsum[blockIdx.x] = s + woff;
}
__global__ void k_scan3() {
    __shared__ int ws[8];
    int tid = threadIdx.x, lane = tid & 31, w = tid >> 5;
    int b = blockIdx.x;
    int v = (tid < b) ? g_bsum[tid] : 0;   // b <= NB-1 < 256
#pragma unroll
    for (int off = 16; off >= 1; off >>= 1) v += __shfl_xor_sync(0xffffffff, v, off);
    if (lane == 0) ws[w] = v;
    __syncthreads();
    int prev = 0;
#pragma unroll
    for (int k = 0; k < 8; k++) prev += ws[k];
    int i = b * 256 + tid;
    if (i < NN) g_cursor[i] = g_off[i] + prev;
}

// ---------------- 4) scatter (2 edges/thread): 8B records {src, as01:half2} ----------------
__global__ void k_scatter(const int* __restrict__ ei) {
    int e2 = blockIdx.x * blockDim.x + threadIdx.x;
    if (e2 >= EE / 2) return;
    int2 ss = __ldg((const int2*)ei + e2);
    int2 dd = __ldg((const int2*)(ei + EE) + e2);
    float2 a0 = __ldg((const float2*)(g_asrc + 2 * ss.x));
    float2 a1 = __ldg((const float2*)(g_asrc + 2 * ss.y));
    __half2 h0 = __floats2half2_rn(a0.x, a0.y);
    __half2 h1 = __floats2half2_rn(a1.x, a1.y);
    int p0 = atomicAdd(&g_cursor[dd.x], 1);
    int p1 = atomicAdd(&g_cursor[dd.y], 1);
    uint2 r0; r0.x = (unsigned)ss.x; r0.y = *(unsigned*)&h0;
    uint2 r1; r1.x = (unsigned)ss.y; r1.y = *(unsigned*)&h1;
    g_sorted[p0] = r0;
    g_sorted[p1] = r1;
}

// ---------------- 5) gather: one warp per dst, lane-sliced record loads, pipelined ----------------
__global__ void k_gather(float* __restrict__ out, const float* __restrict__ bias,
                         const float* __restrict__ esc) {
    int warp_in_block = threadIdx.x >> 5;
    int lane = threadIdx.x & 31;
    int n = blockIdx.x * 8 + warp_in_block;
    if (n >= NN) return;

    int head = lane >> 4;                 // lanes 0-15: head0, 16-31: head1
    int cnt   = g_deg[n];
    int start = g_cursor[n] - cnt;        // cursor is end-of-segment after scatter

    float2 adv = __ldg((const float2*)(g_adst + 2 * n));
    int t16 = lane & 15;
    int qq  = t16 >> 1;                   // record slot (0..7) this lane exps
    int hs  = t16 & 1;                    // head slot
    float ad_sel = hs ? adv.y : adv.x;
    float ad_me  = head ? adv.y : adv.x;

    float2 acc = make_float2(0.0f, 0.0f);
    float den = 0.0f;
    const __half2* hh = (const __half2*)g_hh;
    const uint2* rec = g_sorted + start;

    int nq = cnt >> 3, rem = cnt & 7;
    int l8 = lane & 7;
    uint2 myr;                            // lane l8 holds record l8 of current batch
    if (nq) myr = __ldg(rec + l8);
    for (int q = 0; q < nq; q++) {
        unsigned s[8];
#pragma unroll
        for (int i = 0; i < 8; i++) s[i] = __shfl_sync(0xffffffff, myr.x, i);
        __half2 v[8];
#pragma unroll
        for (int i = 0; i < 8; i++) v[i] = __ldg(hh + (size_t)s[i] * 32 + lane);

        unsigned ab = __shfl_sync(0xffffffff, myr.y, qq);
        float2 af = __half22float2(*(__half2*)&ab);
        float ev = __expf(lrelu((hs ? af.y : af.x) + ad_sel));
        float e[8];
#pragma unroll
        for (int i = 0; i < 8; i++) e[i] = __shfl_sync(0xffffffff, ev, 2 * i + head);

        bool more = (q + 1 < nq);
        uint2 nmyr;
        if (more) nmyr = __ldg(rec + 8 * (q + 1) + l8);

#pragma unroll
        for (int i = 0; i < 8; i++) {
            float2 f = __half22float2(v[i]);
            acc.x += e[i] * f.x;
            acc.y += e[i] * f.y;
            den   += e[i];
        }
        if (more) myr = nmyr;
    }
    const uint2* tp = rec + nq * 8;
    for (int k = 0; k < rem; k++) {
        uint2 rr = __ldg(tp + k);
        __half2 v = __ldg(hh + (size_t)rr.x * 32 + lane);
        float2 af = __half22float2(*(__half2*)&rr.y);
        float e0 = __expf(lrelu((head ? af.y : af.x) + ad_me));
        float2 f = __half22float2(v);
        acc.x += e0 * f.x; acc.y += e0 * f.y;
        den += e0;
    }

    // self loop (fp32 logits)
    float a_self = lrelu(g_asrc[2*n + head] + ad_me);
    float e_self = __expf(a_self);
    float2 hsv = __half22float2(__ldg(hh + (size_t)n * 32 + lane));
    acc.x += e_self * hsv.x; acc.y += e_self * hsv.y;
    den += e_self;

    float rd = __frcp_rn(den);

    float2 nwc = g_nwcnt[n];
    float nw = nwc.x / fmaxf(nwc.y, 1.0f);
    nw = fminf(fmaxf(nw, 0.2f), 5.0f);
    float sf  = 0.1f / (1.0f + __expf(-esc[0]));
    float add = sf * (nw - 1.0f);

    float2 b2 = *(const float2*)(bias + 2 * lane);
    float2 o;
    o.x = acc.x * rd + b2.x + add;
    o.y = acc.y * rd + b2.y + add;
    *(float2*)(out + (size_t)n * HC + 2 * lane) = o;
}

extern "C" void kernel_launch(void* const* d_in, const int* in_sizes, int n_in,
                              void* d_out, int out_size) {
    const float* x       = (const float*)d_in[0];
    const int*   ei      = (const int*)  d_in[1];
    const float* wgt     = (const float*)d_in[2];
    const float* W       = (const float*)d_in[3];
    const float* att_src = (const float*)d_in[4];
    const float* att_dst = (const float*)d_in[5];
    const float* bias    = (const float*)d_in[6];
    const float* esc     = (const float*)d_in[7];
    float* out = (float*)d_out;
    (void)in_sizes; (void)n_in; (void)out_size;

    static int smem_set = 0;
    if (!smem_set) {
        cudaFuncSetAttribute(k_gemm_tc, cudaFuncAttributeMaxDynamicSharedMemorySize,
                             SMEM_FLOATS * 4);
        smem_set = 1;
    }

    k_gemm_tc <<<GB, 256, SMEM_FLOATS * 4>>>(x, W, att_src, att_dst);
    k_hist    <<<(EE / 2 + 255) / 256, 256>>>(ei, wgt);
    k_scan1   <<<NB,                   256>>>();
    k_scan3   <<<NB,                   256>>>();
    k_scatter <<<(EE / 2 + 255) / 256, 256>>>(ei);
    k_gather  <<<(NN + 7) / 8,         256>>>(out, bias, esc);
}

// round 17
// speedup vs baseline: 1.7052x; 1.0301x over previous
#include <cuda_runtime.h>
#include <cuda_fp16.h>
#include <mma.h>
#include <math.h>

using namespace nvcuda;

#define NN 50000
#define EE 1600000
#define DD 128
#define HC 64     // H*C = 2*32
#define NB 196    // ceil(NN/256) scan blocks
#define GB 391    // ceil(NN/128) gemm blocks
#define XSTRIDE 40
#define SMEM_FLOATS (8192 + 128 * XSTRIDE)

// ---- scratch (device globals; no allocation allowed) ----
__device__ __half  g_hh[NN * HC];       // fp16 h = elu(x) @ W      6.4 MB
__device__ float   g_asrc[NN * 2];
__device__ float   g_adst[NN * 2];
__device__ float2  g_nwcnt[NN];         // {sum w, count} per source node
__device__ int     g_deg[NN];           // in-degree (excl self loop)
__device__ int     g_off[NN];           // segment start (arrival-order base)
__device__ int     g_cursor[NN];        // scatter cursors (= segment end after scatter)
__device__ int     g_total;             // arrival-order base counter
__device__ uint2   g_sorted[EE];        // {src, as01:half2}  12.8 MB

__device__ __forceinline__ float lrelu(float a) { return a > 0.0f ? a : 0.2f * a; }
__device__ __forceinline__ float elu_f(float v) { return v > 0.0f ? v : (__expf(v) - 1.0f); }

// ---------------- 1) h = elu(x) @ W via tf32 wmma; fused dots + fp16 mirror ----------------
__global__ void k_gemm_tc(const float* __restrict__ x, const float* __restrict__ W,
                          const float* __restrict__ att_src, const float* __restrict__ att_dst) {
    extern __shared__ float sm[];
    float* sW   = sm;                    // [128][64]  (tf32-rounded)
    float* sX   = sm + 8192;             // [128][XSTRIDE]
    float* sOut = sm;                    // reuses sW after MMAs

    int tid  = threadIdx.x;              // 256 threads = 8 warps
    int wid  = tid >> 5;
    int rb   = blockIdx.x * 128;

    {
        const float4* Wv = (const float4*)W;
        float4* sWv = (float4*)sW;
#pragma unroll
        for (int i = 0; i < 8; i++) {
            float4 v = Wv[tid + i * 256];
            v.x = wmma::__float_to_tf32(v.x);
            v.y = wmma::__float_to_tf32(v.y);
            v.z = wmma::__float_to_tf32(v.z);
            v.w = wmma::__float_to_tf32(v.w);
            sWv[tid + i * 256] = v;
        }
    }

    wmma::fragment<wmma::accumulator, 16, 16, 8, float> acc[4];
#pragma unroll
    for (int f = 0; f < 4; f++) wmma::fill_fragment(acc[f], 0.0f);

    for (int chunk = 0; chunk < 4; chunk++) {
        __syncthreads();
#pragma unroll
        for (int i = 0; i < 4; i++) {
            int idx = tid + i * 256;
            int row = idx >> 3;
            int c4  = idx & 7;
            int gr  = rb + row; if (gr >= NN) gr = NN - 1;
            float4 v = __ldg((const float4*)(x + (size_t)gr * DD + chunk * 32 + c4 * 4));
            v.x = wmma::__float_to_tf32(elu_f(v.x));
            v.y = wmma::__float_to_tf32(elu_f(v.y));
            v.z = wmma::__float_to_tf32(elu_f(v.z));
            v.w = wmma::__float_to_tf32(elu_f(v.w));
            *(float4*)(sX + row * XSTRIDE + c4 * 4) = v;
        }
        __syncthreads();

#pragma unroll
        for (int ks = 0; ks < 4; ks++) {
            wmma::fragment<wmma::matrix_a, 16, 16, 8, wmma::precision::tf32, wmma::row_major> af;
            wmma::load_matrix_sync(af, sX + wid * 16 * XSTRIDE + ks * 8, XSTRIDE);
#pragma unroll
            for (int nf = 0; nf < 4; nf++) {
                wmma::fragment<wmma::matrix_b, 16, 16, 8, wmma::precision::tf32, wmma::row_major> bf;
                wmma::load_matrix_sync(bf, sW + (chunk * 32 + ks * 8) * HC + nf * 16, HC);
                wmma::mma_sync(acc[nf], af, bf, acc[nf]);
            }
        }
    }
    __syncthreads();
#pragma unroll
    for (int nf = 0; nf < 4; nf++)
        wmma::store_matrix_sync(sOut + wid * 16 * HC + nf * 16, acc[nf], HC, wmma::mem_row_major);
    __syncthreads();

    {
        int row  = tid >> 1;
        int head = tid & 1;
        int r = rb + row;
        if (r < NN) {
            const float* hrow = sOut + row * HC + head * 32;
            float as = 0.0f, ad = 0.0f;
            __half2 hv[16];
#pragma unroll
            for (int k = 0; k < 32; k += 2) {
                float h0 = hrow[k], h1 = hrow[k + 1];
                as += h0 * __ldg(att_src + head * 32 + k) + h1 * __ldg(att_src + head * 32 + k + 1);
                ad += h0 * __ldg(att_dst + head * 32 + k) + h1 * __ldg(att_dst + head * 32 + k + 1);
                hv[k >> 1] = __floats2half2_rn(h0, h1);
            }
            g_asrc[2 * r + head] = as;
            g_adst[2 * r + head] = ad;
            uint4* hp = (uint4*)(g_hh + (size_t)r * HC + head * 32);
#pragma unroll
            for (int q = 0; q < 4; q++)
                hp[q] = make_uint4(*(unsigned*)&hv[4*q], *(unsigned*)&hv[4*q+1],
                                   *(unsigned*)&hv[4*q+2], *(unsigned*)&hv[4*q+3]);
            if (head == 0) { g_nwcnt[r] = make_float2(0.0f, 0.0f); g_deg[r] = 0; }
        }
    }
}

// ---------------- 2) histogram (dst only, 2 edges/thread): deg[dst]++ ----------------
__global__ void k_hist(const int* __restrict__ ei) {
    int e2 = blockIdx.x * blockDim.x + threadIdx.x;
    if (e2 == 0) g_total = 0;             // reset arrival-order base before k_scan
    if (e2 >= EE / 2) return;
    int2 dd = __ldg((const int2*)(ei + EE) + e2);
    atomicAdd(&g_deg[dd.x], 1);
    atomicAdd(&g_deg[dd.y], 1);
}

// ---------------- 3) single-kernel scan, arrival-order base ----------------
__global__ void k_scan() {
    int tid = threadIdx.x, lane = tid & 31, w = tid >> 5;
    int i = blockIdx.x * 256 + tid;
    int v = (i < NN) ? g_deg[i] : 0;
    int s = v;
#pragma unroll
    for (int off = 1; off < 32; off <<= 1) {
        int t = __shfl_up_sync(0xffffffff, s, off);
        if (lane >= off) s += t;
    }
    __shared__ int ws[8];
    __shared__ int s_base;
    if (lane == 31) ws[w] = s;
    __syncthreads();
    int woff = 0;
#pragma unroll
    for (int k = 0; k < 8; k++) woff += (k < w) ? ws[k] : 0;
    if (tid == 255) s_base = atomicAdd(&g_total, s + woff);  // block total = s + woff
    __syncthreads();
    if (i < NN) {
        int start = s - v + woff + s_base;
        g_off[i] = start;
        g_cursor[i] = start;
    }
}

// ---------------- 4) scatter (2 edges/thread): records + nwcnt ----------------
__global__ void k_scatter(const int* __restrict__ ei, const float* __restrict__ wgt) {
    int e2 = blockIdx.x * blockDim.x + threadIdx.x;
    if (e2 >= EE / 2) return;
    int2 ss = __ldg((const int2*)ei + e2);
    int2 dd = __ldg((const int2*)(ei + EE) + e2);
    float2 ww = __ldg((const float2*)wgt + e2);
    float2 a0 = __ldg((const float2*)(g_asrc + 2 * ss.x));
    float2 a1 = __ldg((const float2*)(g_asrc + 2 * ss.y));
    __half2 h0 = __floats2half2_rn(a0.x, a0.y);
    __half2 h1 = __floats2half2_rn(a1.x, a1.y);
    int p0 = atomicAdd(&g_cursor[dd.x], 1);
    int p1 = atomicAdd(&g_cursor[dd.y], 1);
    uint2 r0; r0.x = (unsigned)ss.x; r0.y = *(unsigned*)&h0;
    uint2 r1; r1.x = (unsigned)ss.y; r1.y = *(unsigned*)&h1;
    g_sorted[p0] = r0;
    g_sorted[p1] = r1;
    asm volatile("red.global.add.v2.f32 [%0], {%1,%2};"
                 :: "l"((float*)(g_nwcnt + ss.x)), "f"(ww.x), "f"(1.0f) : "memory");
    asm volatile("red.global.add.v2.f32 [%0], {%1,%2};"
                 :: "l"((float*)(g_nwcnt + ss.y)), "f"(ww.y), "f"(1.0f) : "memory");
}

// ---------------- 5) gather: one warp per dst, lane-sliced record loads, pipelined ----------------
__global__ void k_gather(float* __restrict__ out, const float* __restrict__ bias,
                         const float* __restrict__ esc) {
    int warp_in_block = threadIdx.x >> 5;
    int lane = threadIdx.x & 31;
    int n = blockIdx.x * 8 + warp_in_block;
    if (n >= NN) return;

    int head = lane >> 4;                 // lanes 0-15: head0, 16-31: head1
    int start = g_off[n];
    int cnt   = g_cursor[n] - start;      // cursor = end after scatter

    float2 adv = __ldg((const float2*)(g_adst + 2 * n));
    int t16 = lane & 15;
    int qq  = t16 >> 1;
    int hs  = t16 & 1;
    float ad_sel = hs ? adv.y : adv.x;
    float ad_me  = head ? adv.y : adv.x;

    float2 acc = make_float2(0.0f, 0.0f);
    float den = 0.0f;
    const __half2* hh = (const __half2*)g_hh;
    const uint2* rec = g_sorted + start;

    int nq = cnt >> 3, rem = cnt & 7;
    int l8 = lane & 7;
    uint2 myr;
    if (nq) myr = __ldg(rec + l8);
    for (int q = 0; q < nq; q++) {
        unsigned s[8];
#pragma unroll
        for (int i = 0; i < 8; i++) s[i] = __shfl_sync(0xffffffff, myr.x, i);
        __half2 v[8];
#pragma unroll
        for (int i = 0; i < 8; i++) v[i] = __ldg(hh + (size_t)s[i] * 32 + lane);

        unsigned ab = __shfl_sync(0xffffffff, myr.y, qq);
        float2 af = __half22float2(*(__half2*)&ab);
        float ev = __expf(lrelu((hs ? af.y : af.x) + ad_sel));
        float e[8];
#pragma unroll
        for (int i = 0; i < 8; i++) e[i] = __shfl_sync(0xffffffff, ev, 2 * i + head);

        bool more = (q + 1 < nq);
        uint2 nmyr;
        if (more) nmyr = __ldg(rec + 8 * (q + 1) + l8);

#pragma unroll
        for (int i = 0; i < 8; i++) {
            float2 f = __half22float2(v[i]);
            acc.x += e[i] * f.x;
            acc.y += e[i] * f.y;
            den   += e[i];
        }
        if (more) myr = nmyr;
    }
    const uint2* tp = rec + nq * 8;
    for (int k = 0; k < rem; k++) {
        uint2 rr = __ldg(tp + k);
        __half2 v = __ldg(hh + (size_t)rr.x * 32 + lane);
        float2 af = __half22float2(*(__half2*)&rr.y);
        float e0 = __expf(lrelu((head ? af.y : af.x) + ad_me));
        float2 f = __half22float2(v);
        acc.x += e0 * f.x; acc.y += e0 * f.y;
        den += e0;
    }

    // self loop (fp32 logits)
    float a_self = lrelu(g_asrc[2*n + head] + ad_me);
    float e_self = __expf(a_self);
    float2 hsv = __half22float2(__ldg(hh + (size_t)n * 32 + lane));
    acc.x += e_self * hsv.x; acc.y += e_self * hsv.y;
    den += e_self;

    float rd = __frcp_rn(den);

    float2 nwc = g_nwcnt[n];
    float nw = nwc.x / fmaxf(nwc.y, 1.0f);
    nw = fminf(fmaxf(nw, 0.2f), 5.0f);
    float sf  = 0.1f / (1.0f + __expf(-esc[0]));
    float add = sf * (nw - 1.0f);

    float2 b2 = *(const float2*)(bias + 2 * lane);
    float2 o;
    o.x = acc.x * rd + b2.x + add;
    o.y = acc.y * rd + b2.y + add;
    *(float2*)(out + (size_t)n * HC + 2 * lane) = o;
}

extern "C" void kernel_launch(void* const* d_in, const int* in_sizes, int n_in,
                              void* d_out, int out_size) {
    const float* x       = (const float*)d_in[0];
    const int*   ei      = (const int*)  d_in[1];
    const float* wgt     = (const float*)d_in[2];
    const float* W       = (const float*)d_in[3];
    const float* att_src = (const float*)d_in[4];
    const float* att_dst = (const float*)d_in[5];
    const float* bias    = (const float*)d_in[6];
    const float* esc     = (const float*)d_in[7];
    float* out = (float*)d_out;
    (void)in_sizes; (void)n_in; (void)out_size;

    static int smem_set = 0;
    if (!smem_set) {
        cudaFuncSetAttribute(k_gemm_tc, cudaFuncAttributeMaxDynamicSharedMemorySize,
                             SMEM_FLOATS * 4);
        smem_set = 1;
    }

    k_gemm_tc <<<GB, 256, SMEM_FLOATS * 4>>>(x, W, att_src, att_dst);
    k_hist    <<<(EE / 2 + 255) / 256, 256>>>(ei);
    k_scan    <<<NB,                   256>>>();
    k_scatter <<<(EE / 2 + 255) / 256, 256>>>(ei, wgt);
    k_gather  <<<(NN + 7) / 8,         256>>>(out, bias, esc);
}